// round 10
// baseline (speedup 1.0000x reference)
#include <cuda_runtime.h>
#include <stdint.h>

#define BW 4096
#define P_C 16769025u   // 4095*4095
#define P_E 16760836u   // 4094*4094
#define ROWS 4          // output rows per block

__global__ void __launch_bounds__(256)
motif_kernel(const int* __restrict__ board, float* __restrict__ out)
{
    const int i0   = blockIdx.x * ROWS;   // first output row of this block
    const int t    = threadIdx.x;         // 0..255
    const int lane = t & 31;
    const int wd   = t >> 5;
    const int c0   = t << 4;              // mask word t covers cols c0..c0+23
    const int prot = blockIdx.x & 7;      // per-block plane-order rotation

    // ---- Phase 1: build 24-bit bitmasks for board rows i0 .. i0+ROWS+1 ----
    uint32_t b[ROWS + 2], w[ROWS + 2];
#pragma unroll
    for (int r = 0; r < ROWS + 2; ++r) {
        uint32_t bb = 0, ww = 0;
        const int* rp = board + (size_t)(i0 + r) * BW;
        const bool rowok = (i0 + r) < BW;
#pragma unroll
        for (int k = 0; k < 6; ++k) {
            const int col = c0 + 4 * k;
            if (rowok && col < BW) {
                int4 v = *reinterpret_cast<const int4*>(rp + col);
                uint32_t pw = (uint32_t)v.x | ((uint32_t)v.y << 8)
                            | ((uint32_t)v.z << 16) | ((uint32_t)v.w << 24);
                uint32_t bn = ((pw & 0x01010101u) * 0x01020408u) >> 24;
                uint32_t wn = (((pw >> 1) & 0x01010101u) * 0x01020408u) >> 24;
                bb |= bn << (4 * k);
                ww |= wn << (4 * k);
            }
        }
        b[r] = bb; w[r] = ww;
    }

    // ---- Phase 2: per row, compute 8 plane masks in regs, store via SHFL ----
#pragma unroll
    for (int ro = 0; ro < ROWS; ++ro) {
        const int i = i0 + ro;
        if (i >= 4095) break;

        const uint32_t e0 = ~(b[ro] | w[ro]);
        const uint32_t e1 = ~(b[ro + 1] | w[ro + 1]);
        const uint32_t anyE = e0 | (e0 >> 1) | e1 | (e1 >> 1);

        uint32_t pm[8];
        {   // black
            uint32_t A = b[ro], B = b[ro] >> 1, C = b[ro + 1], D = b[ro + 1] >> 1;
            uint32_t AB = A & B, CD = C & D, AD = A & D, BC = B & C;
            uint32_t ge2 = AB | CD | AD | BC | (A & C) | (B & D);
            uint32_t ge3 = (AB & (C | D)) | (CD & (A | B));
            uint32_t eq4 = AB & CD;
            pm[0] = (AD & (e0 >> 1) & e1) | (BC & e0 & (e1 >> 1));   // bamboo_b
            pm[2] = ge2 & anyE;                                      // tiger_b
            pm[4] = ge3 & ~eq4 & anyE;                               // triangle_b
            pm[6] = (e1 >> 1) & (b[ro] >> 1) & (b[ro + 2] >> 1)
                  & b[ro + 1] & (b[ro + 1] >> 2);                    // eye_b
        }
        {   // white
            uint32_t A = w[ro], B = w[ro] >> 1, C = w[ro + 1], D = w[ro + 1] >> 1;
            uint32_t AB = A & B, CD = C & D, AD = A & D, BC = B & C;
            uint32_t ge2 = AB | CD | AD | BC | (A & C) | (B & D);
            uint32_t ge3 = (AB & (C | D)) | (CD & (A | B));
            uint32_t eq4 = AB & CD;
            pm[1] = (AD & (e0 >> 1) & e1) | (BC & e0 & (e1 >> 1));   // bamboo_w
            pm[3] = ge2 & anyE;                                      // tiger_w
            pm[5] = ge3 & ~eq4 & anyE;                               // triangle_w
            pm[7] = (e1 >> 1) & (w[ro] >> 1) & (w[ro + 2] >> 1)
                  & w[ro + 1] & (w[ro + 1] >> 2);                    // eye_w
        }

        // ---- Stores: plane order rotated per block to decorrelate write bursts ----
#pragma unroll
        for (int p = 0; p < 8; ++p) {
            const int pr = (p + prot) & 7;     // rotated plane index
            int rw; size_t gb;
            if (pr < 6) {
                rw = 4095;
                gb = (size_t)pr * P_C + (size_t)i * 4095u;
            } else {
                if (i >= 4094) continue;   // eye planes: 4094 rows
                rw = 4094;
                gb = 6 * (size_t)P_C + (size_t)(pr - 6) * P_E + (size_t)i * 4094u;
            }
            const int h  = (4 - (int)(gb & 3)) & 3;   // scalar head floats
            const int Nv = (rw - h) >> 2;             // aligned float4 count
            float* gp = out + gb;

            if (t == 0)
                for (int c = 0; c < h; ++c)
                    gp[c] = (float)((pm[pr] >> c) & 1u);
#pragma unroll
            for (int q = 0; q < 4; ++q) {
                const int vi = (wd << 7) + (q << 5) + lane;   // coalesced in warp
                const int cb = h + (vi << 2);                 // first col of vector
                const int owner = (cb >> 4) & 31;             // same-warp owner lane
                const uint32_t mo = __shfl_sync(0xffffffffu, pm[pr], owner);
                const uint32_t nib = (mo >> (cb & 15)) & 0xFu; // shift<=18 < 24 bits
                if (vi < Nv) {
                    float4 v;
                    v.x = __uint_as_float((nib & 1u)        * 0x3F800000u);
                    v.y = __uint_as_float(((nib >> 1) & 1u) * 0x3F800000u);
                    v.z = __uint_as_float(((nib >> 2) & 1u) * 0x3F800000u);
                    v.w = __uint_as_float(((nib >> 3) & 1u) * 0x3F800000u);
                    __stcs(reinterpret_cast<float4*>(gp + cb), v);  // streaming store
                }
            }
            if (t == 255)    // tail: cols h+4*Nv .. rw-1, bits relative to word 255
                for (int c = h + (Nv << 2); c < rw; ++c)
                    gp[c] = (float)((pm[pr] >> (c - 4080)) & 1u);
        }
    }
}

extern "C" void kernel_launch(void* const* d_in, const int* in_sizes, int n_in,
                              void* d_out, int out_size)
{
    const int* board = (const int*)d_in[0];
    float* out = (float*)d_out;
    motif_kernel<<<(4095 + ROWS - 1) / ROWS, 256>>>(board, out);
}

// round 11
// speedup vs baseline: 1.0754x; 1.0754x over previous
#include <cuda_runtime.h>
#include <stdint.h>

#define BW 4096
#define P_C 16769025u   // 4095*4095
#define P_E 16760836u   // 4094*4094
#define ROWS 4          // output rows per block

__global__ void __launch_bounds__(256)
motif_kernel(const int* __restrict__ board, float* __restrict__ out)
{
    const int i0   = blockIdx.x * ROWS;   // first output row of this block
    const int t    = threadIdx.x;         // 0..255
    const int lane = t & 31;
    const int wd   = t >> 5;
    const int c0   = t << 4;              // mask word t covers cols c0..c0+23

    // ---- Phase 1: build 24-bit bitmasks for board rows i0 .. i0+ROWS+1 ----
    uint32_t b[ROWS + 2], w[ROWS + 2];
#pragma unroll
    for (int r = 0; r < ROWS + 2; ++r) {
        uint32_t bb = 0, ww = 0;
        const int* rp = board + (size_t)(i0 + r) * BW;
        const bool rowok = (i0 + r) < BW;
#pragma unroll
        for (int k = 0; k < 6; ++k) {
            const int col = c0 + 4 * k;
            if (rowok && col < BW) {
                int4 v = *reinterpret_cast<const int4*>(rp + col);
                uint32_t pw = (uint32_t)v.x | ((uint32_t)v.y << 8)
                            | ((uint32_t)v.z << 16) | ((uint32_t)v.w << 24);
                uint32_t bn = ((pw & 0x01010101u) * 0x01020408u) >> 24;
                uint32_t wn = (((pw >> 1) & 0x01010101u) * 0x01020408u) >> 24;
                bb |= bn << (4 * k);
                ww |= wn << (4 * k);
            }
        }
        b[r] = bb; w[r] = ww;
    }

    // ---- Phase 2: per row, compute 8 plane masks in regs, store via SHFL ----
#pragma unroll
    for (int ro = 0; ro < ROWS; ++ro) {
        const int i = i0 + ro;
        if (i >= 4095) break;

        const uint32_t e0 = ~(b[ro] | w[ro]);
        const uint32_t e1 = ~(b[ro + 1] | w[ro + 1]);
        const uint32_t anyE = e0 | (e0 >> 1) | e1 | (e1 >> 1);

        uint32_t pm[8];
        {   // black
            uint32_t A = b[ro], B = b[ro] >> 1, C = b[ro + 1], D = b[ro + 1] >> 1;
            uint32_t AB = A & B, CD = C & D, AD = A & D, BC = B & C;
            uint32_t ge2 = AB | CD | AD | BC | (A & C) | (B & D);
            uint32_t ge3 = (AB & (C | D)) | (CD & (A | B));
            uint32_t eq4 = AB & CD;
            pm[0] = (AD & (e0 >> 1) & e1) | (BC & e0 & (e1 >> 1));   // bamboo_b
            pm[2] = ge2 & anyE;                                      // tiger_b
            pm[4] = ge3 & ~eq4 & anyE;                               // triangle_b
            pm[6] = (e1 >> 1) & (b[ro] >> 1) & (b[ro + 2] >> 1)
                  & b[ro + 1] & (b[ro + 1] >> 2);                    // eye_b
        }
        {   // white
            uint32_t A = w[ro], B = w[ro] >> 1, C = w[ro + 1], D = w[ro + 1] >> 1;
            uint32_t AB = A & B, CD = C & D, AD = A & D, BC = B & C;
            uint32_t ge2 = AB | CD | AD | BC | (A & C) | (B & D);
            uint32_t ge3 = (AB & (C | D)) | (CD & (A | B));
            uint32_t eq4 = AB & CD;
            pm[1] = (AD & (e0 >> 1) & e1) | (BC & e0 & (e1 >> 1));   // bamboo_w
            pm[3] = ge2 & anyE;                                      // tiger_w
            pm[5] = ge3 & ~eq4 & anyE;                               // triangle_w
            pm[7] = (e1 >> 1) & (w[ro] >> 1) & (w[ro + 2] >> 1)
                  & w[ro + 1] & (w[ro + 1] >> 2);                    // eye_w
        }

        // ---- Stores: warp wd covers cols [512*wd, 512*wd+512); owner lane in-warp ----
#pragma unroll
        for (int p = 0; p < 8; ++p) {
            int rw; size_t gb;
            if (p < 6) {
                rw = 4095;
                gb = (size_t)p * P_C + (size_t)i * 4095u;
            } else {
                if (i >= 4094) break;    // eye planes: 4094 rows
                rw = 4094;
                gb = 6 * (size_t)P_C + (size_t)(p - 6) * P_E + (size_t)i * 4094u;
            }
            const int h  = (4 - (int)(gb & 3)) & 3;   // scalar head floats
            const int Nv = (rw - h) >> 2;             // aligned float4 count
            float* gp = out + gb;

            if (t == 0)
                for (int c = 0; c < h; ++c)
                    gp[c] = (float)((pm[p] >> c) & 1u);
#pragma unroll
            for (int q = 0; q < 4; ++q) {
                const int vi = (wd << 7) + (q << 5) + lane;   // coalesced in warp
                const int cb = h + (vi << 2);                 // first col of vector
                const int owner = (cb >> 4) & 31;             // same-warp owner lane
                const uint32_t mo = __shfl_sync(0xffffffffu, pm[p], owner);
                const uint32_t nib = (mo >> (cb & 15)) & 0xFu; // shift<=18 < 24 bits
                if (vi < Nv) {
                    float4 v;
                    v.x = __uint_as_float((nib & 1u)        * 0x3F800000u);
                    v.y = __uint_as_float(((nib >> 1) & 1u) * 0x3F800000u);
                    v.z = __uint_as_float(((nib >> 2) & 1u) * 0x3F800000u);
                    v.w = __uint_as_float(((nib >> 3) & 1u) * 0x3F800000u);
                    __stcs(reinterpret_cast<float4*>(gp + cb), v);  // streaming store
                }
            }
            if (t == 255)    // tail: cols h+4*Nv .. rw-1, bits relative to word 255
                for (int c = h + (Nv << 2); c < rw; ++c)
                    gp[c] = (float)((pm[p] >> (c - 4080)) & 1u);
        }
    }
}

extern "C" void kernel_launch(void* const* d_in, const int* in_sizes, int n_in,
                              void* d_out, int out_size)
{
    const int* board = (const int*)d_in[0];
    float* out = (float*)d_out;
    motif_kernel<<<(4095 + ROWS - 1) / ROWS, 256>>>(board, out);
}